// round 2
// baseline (speedup 1.0000x reference)
#include <cuda_runtime.h>
#include <cstdint>
#include <math.h>

#define NUI 4096
#define NVI 4096
#define NC 5
#define H0 256
#define H1 128
#define DIN 512
#define SIDE 1024
#define NE 4096          // length of gathered u / v index lists
#define CATW (H0 + DIN)  // 768

// ---------------- scratch (static device globals; no runtime allocation) ----------------
__device__ uint8_t d_code[(size_t)NUI * NVI];   // code[U,V] in {0..5}
__device__ uint8_t d_cg [(size_t)NE * NE];      // gathered code[u[i], v[j]]
__device__ uint8_t d_cgT[(size_t)NE * NE];      // transpose of d_cg
__device__ float   d_cu [(size_t)NC * NUI * H0];
__device__ float   d_cv [(size_t)NC * NVI * H0];
__device__ float   d_ucat[(size_t)NE * CATW];
__device__ float   d_vcat[(size_t)NE * CATW];
__device__ float   d_uh [(size_t)NE * H1];
__device__ float   d_vh [(size_t)NE * H1];
__device__ float   d_T0 [(size_t)NE * H1];
__device__ float   d_T1 [(size_t)NE * H1];
__device__ float   d_PT [2 * H1 * H1];
__device__ double  g_loss, g_se;
__device__ int     g_cnt;

// ---------------- 1. build code matrix from adj (one-hot along c) ----------------
__global__ void code_kernel(const float4* __restrict__ adj) {
    size_t t = (size_t)blockIdx.x * 256 + threadIdx.x;  // over 16M/4 float4 groups
    const size_t S4 = (size_t)NUI * NVI / 4;
    int gx = 0, gy = 0, gz = 0, gw = 0;
#pragma unroll
    for (int c = 0; c < NC; ++c) {
        float4 vv = adj[(size_t)c * S4 + t];
        if (vv.x > 0.5f) gx = c + 1;
        if (vv.y > 0.5f) gy = c + 1;
        if (vv.z > 0.5f) gz = c + 1;
        if (vv.w > 0.5f) gw = c + 1;
    }
    ((uchar4*)d_code)[t] = make_uchar4((unsigned char)gx, (unsigned char)gy,
                                       (unsigned char)gz, (unsigned char)gw);
}

// ---------------- 2. gather code -> code_g and its transpose ----------------
__global__ void gather_kernel(const int* __restrict__ u, const int* __restrict__ v) {
    __shared__ uint8_t s[32][33];
    int i = blockIdx.y * 32 + threadIdx.y;
    int j = blockIdx.x * 32 + threadIdx.x;
    uint8_t g = d_code[(size_t)u[i] * NVI + v[j]];
    d_cg[(size_t)i * NE + j] = g;
    s[threadIdx.y][threadIdx.x] = g;
    __syncthreads();
    int jj = blockIdx.x * 32 + threadIdx.y;
    int ii = blockIdx.y * 32 + threadIdx.x;
    d_cgT[(size_t)jj * NE + ii] = s[threadIdx.x][threadIdx.y];
}

// ---------------- 3. cumsum of u_w / v_w over rating axis ----------------
__global__ void cumsum_kernel(const float* __restrict__ w, float* __restrict__ out, int n) {
    int idx = blockIdx.x * blockDim.x + threadIdx.x;
    if (idx >= n) return;
    float s = 0.f;
#pragma unroll
    for (int c = 0; c < NC; ++c) {
        s += w[(size_t)c * n + idx];
        out[(size_t)c * n + idx] = s;
    }
}

// ---------------- 4. zero the loss accumulators (every replay) ----------------
__global__ void zero_kernel() {
    g_loss = 0.0; g_se = 0.0; g_cnt = 0;
}

// ---------------- 5. graph conv: one block per output row ----------------
// out_row[h] = relu( (1/cnt) * sum_{j: g>0} csum[(g-1)*4096 + idx[j]][h] )
// cnt == du[i] (or di[j]) by construction. Deterministic order via prefix-sum compaction.
__global__ void conv_kernel(const uint8_t* __restrict__ cg, const int* __restrict__ idx,
                            const float* __restrict__ csum, float* __restrict__ outcat) {
    __shared__ uint8_t rs[NE];
    __shared__ int list[NE];
    __shared__ int cnts[256];
    int i = blockIdx.x, h = threadIdx.x;
    const uint8_t* row = cg + (size_t)i * NE;
    for (int t = h; t < NE / 4; t += 256)
        ((uint32_t*)rs)[t] = ((const uint32_t*)row)[t];
    __syncthreads();

    int j0 = h * 16;
    int local = 0;
#pragma unroll
    for (int t = 0; t < 16; ++t) if (rs[j0 + t]) local++;
    cnts[h] = local;
    __syncthreads();
    // inclusive Hillis-Steele scan over 256
    for (int s = 1; s < 256; s <<= 1) {
        int vv = (h >= s) ? cnts[h - s] : 0;
        __syncthreads();
        cnts[h] += vv;
        __syncthreads();
    }
    int pos = cnts[h] - local;
    int total = cnts[255];
    for (int t = 0; t < 16; ++t) {
        int g = rs[j0 + t];
        if (g) list[pos++] = (g - 1) * NVI + idx[j0 + t];
    }
    __syncthreads();

    float acc = 0.f;
    int jj = 0;
    for (; jj + 4 <= total; jj += 4) {
        float a0 = csum[(size_t)list[jj + 0] * H0 + h];
        float a1 = csum[(size_t)list[jj + 1] * H0 + h];
        float a2 = csum[(size_t)list[jj + 2] * H0 + h];
        float a3 = csum[(size_t)list[jj + 3] * H0 + h];
        acc += a0; acc += a1; acc += a2; acc += a3;
    }
    for (; jj < total; ++jj) acc += csum[(size_t)list[jj] * H0 + h];

    float inv = total ? 1.f / (float)total : 0.f;
    outcat[(size_t)i * CATW + h] = fmaxf(acc * inv, 0.f);
}

// ---------------- generic fp32 tiled GEMM: C[m,n] = relu?(sum_k A[m,k]*B[n,k] + bias[n]) ----
// BM=BN=64, BK=16, 256 threads, 4x4 microtile. Optional row gather on A.
__global__ void gemm_kernel(const float* __restrict__ A, int lda, const int* __restrict__ idxA,
                            const float* __restrict__ B, int ldb,
                            const float* __restrict__ bias,
                            float* __restrict__ C, int ldc,
                            int K, int doRelu) {
    __shared__ float As[16][64];
    __shared__ float Bs[16][64];
    int bm = blockIdx.y * 64, bn = blockIdx.x * 64;
    int tid = threadIdx.x;
    int tx = tid & 15, ty = tid >> 4;
    int lrow = tid >> 2, lk = (tid & 3) * 4;
    int arow = bm + lrow;
    const float* Ap = A + (size_t)(idxA ? idxA[arow] : arow) * lda + lk;
    const float* Bp = B + (size_t)(bn + lrow) * ldb + lk;
    float acc[4][4] = {};
    for (int k0 = 0; k0 < K; k0 += 16) {
        float4 av = *(const float4*)(Ap + k0);
        float4 bv = *(const float4*)(Bp + k0);
        __syncthreads();
        As[lk + 0][lrow] = av.x; As[lk + 1][lrow] = av.y;
        As[lk + 2][lrow] = av.z; As[lk + 3][lrow] = av.w;
        Bs[lk + 0][lrow] = bv.x; Bs[lk + 1][lrow] = bv.y;
        Bs[lk + 2][lrow] = bv.z; Bs[lk + 3][lrow] = bv.w;
        __syncthreads();
#pragma unroll
        for (int k = 0; k < 16; ++k) {
            float4 a = *(const float4*)&As[k][ty * 4];
            float4 b = *(const float4*)&Bs[k][tx * 4];
            float af[4] = {a.x, a.y, a.z, a.w};
            float bf[4] = {b.x, b.y, b.z, b.w};
#pragma unroll
            for (int p = 0; p < 4; ++p)
#pragma unroll
                for (int q = 0; q < 4; ++q)
                    acc[p][q] = fmaf(af[p], bf[q], acc[p][q]);
        }
    }
#pragma unroll
    for (int p = 0; p < 4; ++p) {
        int row = bm + ty * 4 + p;
#pragma unroll
        for (int q = 0; q < 4; ++q) {
            int col = bn + tx * 4 + q;
            float vv = acc[p][q];
            if (bias) vv += bias[col];
            if (doRelu) vv = fmaxf(vv, 0.f);
            C[(size_t)row * ldc + col] = vv;
        }
    }
}

// ---------------- transpose P: PT[b,e,d] = P[b,d,e] ----------------
__global__ void transP_kernel(const float* __restrict__ P) {
    int t = blockIdx.x * 256 + threadIdx.x;  // 2*128*128 = 32768
    int b = t >> 14, rem = t & 16383;
    int d = rem >> 7, e = rem & 127;
    d_PT[(size_t)b * 16384 + e * 128 + d] = P[t];
}

// ---------------- fast exp (FMA-pipe only, no MUFU) ----------------
__device__ __forceinline__ float fast_exp(float x) {
    float t = x * 1.4426950408889634f;
    float r = rintf(t);
    float f = t - r;
    float p = 1.535336188319500e-4f;
    p = fmaf(p, f, 1.339887440266574e-3f);
    p = fmaf(p, f, 9.618437357674640e-3f);
    p = fmaf(p, f, 5.550332471162809e-2f);
    p = fmaf(p, f, 2.402264791363012e-1f);
    p = fmaf(p, f, 6.931472028550421e-1f);
    p = fmaf(p, f, 1.0f);
    int e = (int)r;
    if (e < -126) e = -126;
    return p * __int_as_float((e + 127) << 23);
}

// ---------------- fused decoder: S_b = T_b @ v_h^T, logits, softmax, m_hat, losses -------
__global__ void final_kernel(const float* __restrict__ avec, float* __restrict__ out) {
    __shared__ float As0[16][64], As1[16][64], Bs[16][64];
    int bm = blockIdx.y * 64, bn = blockIdx.x * 64;
    int tid = threadIdx.x;
    int tx = tid & 15, ty = tid >> 4;
    int lrow = tid >> 2, lk = (tid & 3) * 4;
    const float* A0p = d_T0 + (size_t)(bm + lrow) * H1 + lk;
    const float* A1p = d_T1 + (size_t)(bm + lrow) * H1 + lk;
    const float* Bp  = d_vh + (size_t)(bn + lrow) * H1 + lk;
    float acc0[4][4] = {}, acc1[4][4] = {};
    for (int k0 = 0; k0 < H1; k0 += 16) {
        float4 a0 = *(const float4*)(A0p + k0);
        float4 a1 = *(const float4*)(A1p + k0);
        float4 bv = *(const float4*)(Bp + k0);
        __syncthreads();
        As0[lk + 0][lrow] = a0.x; As0[lk + 1][lrow] = a0.y;
        As0[lk + 2][lrow] = a0.z; As0[lk + 3][lrow] = a0.w;
        As1[lk + 0][lrow] = a1.x; As1[lk + 1][lrow] = a1.y;
        As1[lk + 2][lrow] = a1.z; As1[lk + 3][lrow] = a1.w;
        Bs [lk + 0][lrow] = bv.x; Bs [lk + 1][lrow] = bv.y;
        Bs [lk + 2][lrow] = bv.z; Bs [lk + 3][lrow] = bv.w;
        __syncthreads();
#pragma unroll
        for (int k = 0; k < 16; ++k) {
            float4 fa0 = *(const float4*)&As0[k][ty * 4];
            float4 fa1 = *(const float4*)&As1[k][ty * 4];
            float4 fb  = *(const float4*)&Bs [k][tx * 4];
            float a0f[4] = {fa0.x, fa0.y, fa0.z, fa0.w};
            float a1f[4] = {fa1.x, fa1.y, fa1.z, fa1.w};
            float bf [4] = {fb.x,  fb.y,  fb.z,  fb.w};
#pragma unroll
            for (int p = 0; p < 4; ++p)
#pragma unroll
                for (int q = 0; q < 4; ++q) {
                    acc0[p][q] = fmaf(a0f[p], bf[q], acc0[p][q]);
                    acc1[p][q] = fmaf(a1f[p], bf[q], acc1[p][q]);
                }
        }
    }

    float a0c[5], a1c[5];
#pragma unroll
    for (int c = 0; c < 5; ++c) { a0c[c] = avec[c]; a1c[c] = avec[5 + c]; }

    float lloss = 0.f, lsse = 0.f;
    int lcnt = 0;
#pragma unroll
    for (int p = 0; p < 4; ++p) {
        int i = bm + ty * 4 + p;
#pragma unroll
        for (int q = 0; q < 4; ++q) {
            int j = bn + tx * 4 + q;
            float s0 = acc0[p][q], s1 = acc1[p][q];
            float l[5], mx = -1e30f;
#pragma unroll
            for (int c = 0; c < 5; ++c) {
                l[c] = fmaf(a0c[c], s0, a1c[c] * s1);
                mx = fmaxf(mx, l[c]);
            }
            float e[5], ssum = 0.f, mh = 0.f;
#pragma unroll
            for (int c = 0; c < 5; ++c) {
                e[c] = fast_exp(l[c] - mx);
                ssum += e[c];
                mh = fmaf((float)(c + 1), e[c], mh);
            }
            float inv = 1.f / ssum;
            mh *= inv;
            out[(size_t)i * NE + j] = mh;
            int g = d_cg[(size_t)i * NE + j];
            if (g) {
                float lse = mx + logf(ssum);
                // pick l[g-1] without dynamic indexing (stay in registers)
                float lg = l[0];
#pragma unroll
                for (int c = 1; c < 5; ++c) if (g == c + 1) lg = l[c];
                lloss += lse - lg;
                float dd = mh - (float)g;
                lsse += dd * dd;
                lcnt++;
            }
        }
    }

    __shared__ double red[256];
    __shared__ int redi[256];
    __syncthreads();
    red[tid] = (double)lloss; __syncthreads();
    for (int s = 128; s > 0; s >>= 1) { if (tid < s) red[tid] += red[tid + s]; __syncthreads(); }
    if (tid == 0) atomicAdd(&g_loss, red[0]);
    __syncthreads();
    red[tid] = (double)lsse; __syncthreads();
    for (int s = 128; s > 0; s >>= 1) { if (tid < s) red[tid] += red[tid + s]; __syncthreads(); }
    if (tid == 0) atomicAdd(&g_se, red[0]);
    __syncthreads();
    redi[tid] = lcnt; __syncthreads();
    for (int s = 128; s > 0; s >>= 1) { if (tid < s) redi[tid] += redi[tid + s]; __syncthreads(); }
    if (tid == 0) atomicAdd(&g_cnt, redi[0]);
}

// ---------------- scalar finalize ----------------
__global__ void fin_kernel(float* __restrict__ out) {
    double n = (g_cnt > 0) ? (double)g_cnt : 1.0;
    out[(size_t)NE * NE + 0] = (float)(g_loss / n);
    out[(size_t)NE * NE + 1] = (float)sqrt(g_se / n);
}

// ---------------- host launcher (graph-capturable, allocation-free) ----------------
extern "C" void kernel_launch(void* const* d_in, const int* in_sizes, int n_in,
                              void* d_out, int out_size) {
    const int*   u     = (const int*)d_in[0];
    const int*   v     = (const int*)d_in[1];
    // d_in[2] = r (unused by the reference)
    const float* adj   = (const float*)d_in[3];
    const float* ufeat = (const float*)d_in[4];
    const float* vfeat = (const float*)d_in[5];
    const float* u_w   = (const float*)d_in[6];
    const float* v_w   = (const float*)d_in[7];
    const float* Wu1   = (const float*)d_in[8];
    const float* bu1   = (const float*)d_in[9];
    const float* Wv1   = (const float*)d_in[10];
    const float* bv1   = (const float*)d_in[11];
    const float* Wu2   = (const float*)d_in[12];
    const float* Wv2   = (const float*)d_in[13];
    const float* P     = (const float*)d_in[14];
    const float* a     = (const float*)d_in[15];
    float* out = (float*)d_out;

    void* p;
    uint8_t *cg, *cgT;
    float *cu, *cv, *ucat, *vcat, *uh, *vh, *T0, *T1, *PT;
    cudaGetSymbolAddress(&p, d_cg);   cg   = (uint8_t*)p;
    cudaGetSymbolAddress(&p, d_cgT);  cgT  = (uint8_t*)p;
    cudaGetSymbolAddress(&p, d_cu);   cu   = (float*)p;
    cudaGetSymbolAddress(&p, d_cv);   cv   = (float*)p;
    cudaGetSymbolAddress(&p, d_ucat); ucat = (float*)p;
    cudaGetSymbolAddress(&p, d_vcat); vcat = (float*)p;
    cudaGetSymbolAddress(&p, d_uh);   uh   = (float*)p;
    cudaGetSymbolAddress(&p, d_vh);   vh   = (float*)p;
    cudaGetSymbolAddress(&p, d_T0);   T0   = (float*)p;
    cudaGetSymbolAddress(&p, d_T1);   T1   = (float*)p;
    cudaGetSymbolAddress(&p, d_PT);   PT   = (float*)p;

    // 1. adj -> code
    code_kernel<<<16384, 256>>>((const float4*)adj);
    // 2. gathered code matrix + transpose
    gather_kernel<<<dim3(NE / 32, NE / 32), dim3(32, 32)>>>(u, v);
    // 3. rating-axis cumsums
    cumsum_kernel<<<(NUI * H0) / 256, 256>>>(u_w, cu, NUI * H0);
    cumsum_kernel<<<(NVI * H0) / 256, 256>>>(v_w, cv, NVI * H0);
    // 4. zero accumulators (graph replays!)
    zero_kernel<<<1, 1>>>();
    // 5. graph conv (sparse gather-sum); writes z into cat[:, :256]
    conv_kernel<<<NE, 256>>>(cg,  v, cv, ucat);
    conv_kernel<<<NE, 256>>>(cgT, u, cu, vcat);
    // 6. feature MLPs into cat[:, 256:768]
    gemm_kernel<<<dim3(DIN / 64, NE / 64), 256>>>(ufeat, SIDE, u, Wu1, SIDE, bu1,
                                                  ucat + H0, CATW, SIDE, 1);
    gemm_kernel<<<dim3(DIN / 64, NE / 64), 256>>>(vfeat, SIDE, v, Wv1, SIDE, bv1,
                                                  vcat + H0, CATW, SIDE, 1);
    // 7. hidden projections
    gemm_kernel<<<dim3(H1 / 64, NE / 64), 256>>>(ucat, CATW, nullptr, Wu2, CATW, nullptr,
                                                 uh, H1, CATW, 1);
    gemm_kernel<<<dim3(H1 / 64, NE / 64), 256>>>(vcat, CATW, nullptr, Wv2, CATW, nullptr,
                                                 vh, H1, CATW, 1);
    // 8. T_b = u_h @ P[b]
    transP_kernel<<<128, 256>>>(P);
    gemm_kernel<<<dim3(H1 / 64, NE / 64), 256>>>(uh, H1, nullptr, PT, H1, nullptr,
                                                 T0, H1, H1, 0);
    gemm_kernel<<<dim3(H1 / 64, NE / 64), 256>>>(uh, H1, nullptr, PT + H1 * H1, H1, nullptr,
                                                 T1, H1, H1, 0);
    // 9. fused decoder + softmax + losses
    final_kernel<<<dim3(NE / 64, NE / 64), 256>>>(a, out);
    // 10. scalars
    if (out_size >= NE * NE + 2) fin_kernel<<<1, 1>>>(out);
}

// round 3
// speedup vs baseline: 1.0047x; 1.0047x over previous
#include <cuda_runtime.h>
#include <cstdint>
#include <math.h>

#define NUI 4096
#define NVI 4096
#define NC 5
#define H0 256
#define H1 128
#define DIN 512
#define SIDE 1024
#define NE 4096          // length of gathered u / v index lists
#define CATW (H0 + DIN)  // 768

// ---------------- scratch (static device globals; no runtime allocation) ----------------
__device__ uint8_t d_code[(size_t)NUI * NVI];   // code[U,V] in {0..5}
__device__ uint8_t d_cg [(size_t)NE * NE];      // gathered code[u[i], v[j]]
__device__ uint8_t d_cgT[(size_t)NE * NE];      // transpose of d_cg
__device__ float   d_cu [(size_t)NC * NUI * H0];
__device__ float   d_cv [(size_t)NC * NVI * H0];
__device__ float   d_ucat[(size_t)NE * CATW];
__device__ float   d_vcat[(size_t)NE * CATW];
__device__ float   d_uh [(size_t)NE * H1];
__device__ float   d_vh [(size_t)NE * H1];
__device__ float   d_T0 [(size_t)NE * H1];
__device__ float   d_T1 [(size_t)NE * H1];
__device__ float   d_PT [2 * H1 * H1];
__device__ double  g_loss, g_se;
__device__ int     g_cnt;

// ---------------- 1. build code matrix from adj (one-hot along c) ----------------
__global__ void code_kernel(const float4* __restrict__ adj) {
    size_t t = (size_t)blockIdx.x * 256 + threadIdx.x;  // over 16M/4 float4 groups
    const size_t S4 = (size_t)NUI * NVI / 4;
    int gx = 0, gy = 0, gz = 0, gw = 0;
#pragma unroll
    for (int c = 0; c < NC; ++c) {
        float4 vv = adj[(size_t)c * S4 + t];
        if (vv.x > 0.5f) gx = c + 1;
        if (vv.y > 0.5f) gy = c + 1;
        if (vv.z > 0.5f) gz = c + 1;
        if (vv.w > 0.5f) gw = c + 1;
    }
    ((uchar4*)d_code)[t] = make_uchar4((unsigned char)gx, (unsigned char)gy,
                                       (unsigned char)gz, (unsigned char)gw);
}

// ---------------- 2. gather code -> code_g and its transpose ----------------
__global__ void gather_kernel(const int* __restrict__ u, const int* __restrict__ v) {
    __shared__ uint8_t s[32][33];
    int i = blockIdx.y * 32 + threadIdx.y;
    int j = blockIdx.x * 32 + threadIdx.x;
    uint8_t g = d_code[(size_t)u[i] * NVI + v[j]];
    d_cg[(size_t)i * NE + j] = g;
    s[threadIdx.y][threadIdx.x] = g;
    __syncthreads();
    int jj = blockIdx.x * 32 + threadIdx.y;
    int ii = blockIdx.y * 32 + threadIdx.x;
    d_cgT[(size_t)jj * NE + ii] = s[threadIdx.x][threadIdx.y];
}

// ---------------- 3. cumsum of u_w / v_w over rating axis ----------------
__global__ void cumsum_kernel(const float* __restrict__ w, float* __restrict__ out, int n) {
    int idx = blockIdx.x * blockDim.x + threadIdx.x;
    if (idx >= n) return;
    float s = 0.f;
#pragma unroll
    for (int c = 0; c < NC; ++c) {
        s += w[(size_t)c * n + idx];
        out[(size_t)c * n + idx] = s;
    }
}

// ---------------- 4. zero the loss accumulators (every replay) ----------------
__global__ void zero_kernel() {
    g_loss = 0.0; g_se = 0.0; g_cnt = 0;
}

// ---------------- 5. graph conv: one block per output row ----------------
// out_row[h] = relu( (1/cnt) * sum_{j: g>0} csum[(g-1)*4096 + idx[j]][h] )
// cnt == du[i] (or di[j]) by construction. Deterministic order via prefix-sum compaction.
__global__ void conv_kernel(const uint8_t* __restrict__ cg, const int* __restrict__ idx,
                            const float* __restrict__ csum, float* __restrict__ outcat) {
    __shared__ uint8_t rs[NE];
    __shared__ int list[NE];
    __shared__ int cnts[256];
    int i = blockIdx.x, h = threadIdx.x;
    const uint8_t* row = cg + (size_t)i * NE;
    for (int t = h; t < NE / 4; t += 256)
        ((uint32_t*)rs)[t] = ((const uint32_t*)row)[t];
    __syncthreads();

    int j0 = h * 16;
    int local = 0;
#pragma unroll
    for (int t = 0; t < 16; ++t) if (rs[j0 + t]) local++;
    cnts[h] = local;
    __syncthreads();
    // inclusive Hillis-Steele scan over 256
    for (int s = 1; s < 256; s <<= 1) {
        int vv = (h >= s) ? cnts[h - s] : 0;
        __syncthreads();
        cnts[h] += vv;
        __syncthreads();
    }
    int pos = cnts[h] - local;
    int total = cnts[255];
    for (int t = 0; t < 16; ++t) {
        int g = rs[j0 + t];
        if (g) list[pos++] = (g - 1) * NVI + idx[j0 + t];
    }
    __syncthreads();

    float acc = 0.f;
    int jj = 0;
    for (; jj + 4 <= total; jj += 4) {
        float a0 = csum[(size_t)list[jj + 0] * H0 + h];
        float a1 = csum[(size_t)list[jj + 1] * H0 + h];
        float a2 = csum[(size_t)list[jj + 2] * H0 + h];
        float a3 = csum[(size_t)list[jj + 3] * H0 + h];
        acc += a0; acc += a1; acc += a2; acc += a3;
    }
    for (; jj < total; ++jj) acc += csum[(size_t)list[jj] * H0 + h];

    float inv = total ? 1.f / (float)total : 0.f;
    outcat[(size_t)i * CATW + h] = fmaxf(acc * inv, 0.f);
}

// ---------------- generic fp32 tiled GEMM: C[m,n] = relu?(sum_k A[m,k]*B[n,k] + bias[n]) ----
// BM=BN=64, BK=16, 256 threads, 4x4 microtile. Optional row gather on A.
__global__ void gemm_kernel(const float* __restrict__ A, int lda, const int* __restrict__ idxA,
                            const float* __restrict__ B, int ldb,
                            const float* __restrict__ bias,
                            float* __restrict__ C, int ldc,
                            int K, int doRelu) {
    __shared__ float As[16][64];
    __shared__ float Bs[16][64];
    int bm = blockIdx.y * 64, bn = blockIdx.x * 64;
    int tid = threadIdx.x;
    int tx = tid & 15, ty = tid >> 4;
    int lrow = tid >> 2, lk = (tid & 3) * 4;
    int arow = bm + lrow;
    const float* Ap = A + (size_t)(idxA ? idxA[arow] : arow) * lda + lk;
    const float* Bp = B + (size_t)(bn + lrow) * ldb + lk;
    float acc[4][4] = {};
    for (int k0 = 0; k0 < K; k0 += 16) {
        float4 av = *(const float4*)(Ap + k0);
        float4 bv = *(const float4*)(Bp + k0);
        __syncthreads();
        As[lk + 0][lrow] = av.x; As[lk + 1][lrow] = av.y;
        As[lk + 2][lrow] = av.z; As[lk + 3][lrow] = av.w;
        Bs[lk + 0][lrow] = bv.x; Bs[lk + 1][lrow] = bv.y;
        Bs[lk + 2][lrow] = bv.z; Bs[lk + 3][lrow] = bv.w;
        __syncthreads();
#pragma unroll
        for (int k = 0; k < 16; ++k) {
            float4 a = *(const float4*)&As[k][ty * 4];
            float4 b = *(const float4*)&Bs[k][tx * 4];
            float af[4] = {a.x, a.y, a.z, a.w};
            float bf[4] = {b.x, b.y, b.z, b.w};
#pragma unroll
            for (int p = 0; p < 4; ++p)
#pragma unroll
                for (int q = 0; q < 4; ++q)
                    acc[p][q] = fmaf(af[p], bf[q], acc[p][q]);
        }
    }
#pragma unroll
    for (int p = 0; p < 4; ++p) {
        int row = bm + ty * 4 + p;
#pragma unroll
        for (int q = 0; q < 4; ++q) {
            int col = bn + tx * 4 + q;
            float vv = acc[p][q];
            if (bias) vv += bias[col];
            if (doRelu) vv = fmaxf(vv, 0.f);
            C[(size_t)row * ldc + col] = vv;
        }
    }
}

// ---------------- transpose P: PT[b,e,d] = P[b,d,e] ----------------
__global__ void transP_kernel(const float* __restrict__ P) {
    int t = blockIdx.x * 256 + threadIdx.x;  // 2*128*128 = 32768
    int b = t >> 14, rem = t & 16383;
    int d = rem >> 7, e = rem & 127;
    d_PT[(size_t)b * 16384 + e * 128 + d] = P[t];
}

// ---------------- fast exp (FMA-pipe only, no MUFU) ----------------
__device__ __forceinline__ float fast_exp(float x) {
    float t = x * 1.4426950408889634f;
    float r = rintf(t);
    float f = t - r;
    float p = 1.535336188319500e-4f;
    p = fmaf(p, f, 1.339887440266574e-3f);
    p = fmaf(p, f, 9.618437357674640e-3f);
    p = fmaf(p, f, 5.550332471162809e-2f);
    p = fmaf(p, f, 2.402264791363012e-1f);
    p = fmaf(p, f, 6.931472028550421e-1f);
    p = fmaf(p, f, 1.0f);
    int e = (int)r;
    if (e < -126) e = -126;
    return p * __int_as_float((e + 127) << 23);
}

// ---------------- fused decoder: S_b = T_b @ v_h^T, logits, softmax, m_hat, losses -------
__global__ void final_kernel(const float* __restrict__ avec, float* __restrict__ out) {
    __shared__ float As0[16][64], As1[16][64], Bs[16][64];
    int bm = blockIdx.y * 64, bn = blockIdx.x * 64;
    int tid = threadIdx.x;
    int tx = tid & 15, ty = tid >> 4;
    int lrow = tid >> 2, lk = (tid & 3) * 4;
    const float* A0p = d_T0 + (size_t)(bm + lrow) * H1 + lk;
    const float* A1p = d_T1 + (size_t)(bm + lrow) * H1 + lk;
    const float* Bp  = d_vh + (size_t)(bn + lrow) * H1 + lk;
    float acc0[4][4] = {}, acc1[4][4] = {};
    for (int k0 = 0; k0 < H1; k0 += 16) {
        float4 a0 = *(const float4*)(A0p + k0);
        float4 a1 = *(const float4*)(A1p + k0);
        float4 bv = *(const float4*)(Bp + k0);
        __syncthreads();
        As0[lk + 0][lrow] = a0.x; As0[lk + 1][lrow] = a0.y;
        As0[lk + 2][lrow] = a0.z; As0[lk + 3][lrow] = a0.w;
        As1[lk + 0][lrow] = a1.x; As1[lk + 1][lrow] = a1.y;
        As1[lk + 2][lrow] = a1.z; As1[lk + 3][lrow] = a1.w;
        Bs [lk + 0][lrow] = bv.x; Bs [lk + 1][lrow] = bv.y;
        Bs [lk + 2][lrow] = bv.z; Bs [lk + 3][lrow] = bv.w;
        __syncthreads();
#pragma unroll
        for (int k = 0; k < 16; ++k) {
            float4 fa0 = *(const float4*)&As0[k][ty * 4];
            float4 fa1 = *(const float4*)&As1[k][ty * 4];
            float4 fb  = *(const float4*)&Bs [k][tx * 4];
            float a0f[4] = {fa0.x, fa0.y, fa0.z, fa0.w};
            float a1f[4] = {fa1.x, fa1.y, fa1.z, fa1.w};
            float bf [4] = {fb.x,  fb.y,  fb.z,  fb.w};
#pragma unroll
            for (int p = 0; p < 4; ++p)
#pragma unroll
                for (int q = 0; q < 4; ++q) {
                    acc0[p][q] = fmaf(a0f[p], bf[q], acc0[p][q]);
                    acc1[p][q] = fmaf(a1f[p], bf[q], acc1[p][q]);
                }
        }
    }

    float a0c[5], a1c[5];
#pragma unroll
    for (int c = 0; c < 5; ++c) { a0c[c] = avec[c]; a1c[c] = avec[5 + c]; }

    float lloss = 0.f, lsse = 0.f;
    int lcnt = 0;
#pragma unroll
    for (int p = 0; p < 4; ++p) {
        int i = bm + ty * 4 + p;
#pragma unroll
        for (int q = 0; q < 4; ++q) {
            int j = bn + tx * 4 + q;
            float s0 = acc0[p][q], s1 = acc1[p][q];
            float l[5], mx = -1e30f;
#pragma unroll
            for (int c = 0; c < 5; ++c) {
                l[c] = fmaf(a0c[c], s0, a1c[c] * s1);
                mx = fmaxf(mx, l[c]);
            }
            float e[5], ssum = 0.f, mh = 0.f;
#pragma unroll
            for (int c = 0; c < 5; ++c) {
                e[c] = fast_exp(l[c] - mx);
                ssum += e[c];
                mh = fmaf((float)(c + 1), e[c], mh);
            }
            float inv = 1.f / ssum;
            mh *= inv;
            out[(size_t)i * NE + j] = mh;
            int g = d_cg[(size_t)i * NE + j];
            if (g) {
                float lse = mx + logf(ssum);
                // pick l[g-1] without dynamic indexing (stay in registers)
                float lg = l[0];
#pragma unroll
                for (int c = 1; c < 5; ++c) if (g == c + 1) lg = l[c];
                lloss += lse - lg;
                float dd = mh - (float)g;
                lsse += dd * dd;
                lcnt++;
            }
        }
    }

    __shared__ double red[256];
    __shared__ int redi[256];
    __syncthreads();
    red[tid] = (double)lloss; __syncthreads();
    for (int s = 128; s > 0; s >>= 1) { if (tid < s) red[tid] += red[tid + s]; __syncthreads(); }
    if (tid == 0) atomicAdd(&g_loss, red[0]);
    __syncthreads();
    red[tid] = (double)lsse; __syncthreads();
    for (int s = 128; s > 0; s >>= 1) { if (tid < s) red[tid] += red[tid + s]; __syncthreads(); }
    if (tid == 0) atomicAdd(&g_se, red[0]);
    __syncthreads();
    redi[tid] = lcnt; __syncthreads();
    for (int s = 128; s > 0; s >>= 1) { if (tid < s) redi[tid] += redi[tid + s]; __syncthreads(); }
    if (tid == 0) atomicAdd(&g_cnt, redi[0]);
}

// ---------------- scalar finalize ----------------
__global__ void fin_kernel(float* __restrict__ out) {
    double n = (g_cnt > 0) ? (double)g_cnt : 1.0;
    out[(size_t)NE * NE + 0] = (float)(g_loss / n);
    out[(size_t)NE * NE + 1] = (float)sqrt(g_se / n);
}

// ---------------- host launcher (graph-capturable, allocation-free) ----------------
extern "C" void kernel_launch(void* const* d_in, const int* in_sizes, int n_in,
                              void* d_out, int out_size) {
    const int*   u     = (const int*)d_in[0];
    const int*   v     = (const int*)d_in[1];
    // d_in[2] = r (unused by the reference)
    const float* adj   = (const float*)d_in[3];
    const float* ufeat = (const float*)d_in[4];
    const float* vfeat = (const float*)d_in[5];
    const float* u_w   = (const float*)d_in[6];
    const float* v_w   = (const float*)d_in[7];
    const float* Wu1   = (const float*)d_in[8];
    const float* bu1   = (const float*)d_in[9];
    const float* Wv1   = (const float*)d_in[10];
    const float* bv1   = (const float*)d_in[11];
    const float* Wu2   = (const float*)d_in[12];
    const float* Wv2   = (const float*)d_in[13];
    const float* P     = (const float*)d_in[14];
    const float* a     = (const float*)d_in[15];
    float* out = (float*)d_out;

    void* p;
    uint8_t *cg, *cgT;
    float *cu, *cv, *ucat, *vcat, *uh, *vh, *T0, *T1, *PT;
    cudaGetSymbolAddress(&p, d_cg);   cg   = (uint8_t*)p;
    cudaGetSymbolAddress(&p, d_cgT);  cgT  = (uint8_t*)p;
    cudaGetSymbolAddress(&p, d_cu);   cu   = (float*)p;
    cudaGetSymbolAddress(&p, d_cv);   cv   = (float*)p;
    cudaGetSymbolAddress(&p, d_ucat); ucat = (float*)p;
    cudaGetSymbolAddress(&p, d_vcat); vcat = (float*)p;
    cudaGetSymbolAddress(&p, d_uh);   uh   = (float*)p;
    cudaGetSymbolAddress(&p, d_vh);   vh   = (float*)p;
    cudaGetSymbolAddress(&p, d_T0);   T0   = (float*)p;
    cudaGetSymbolAddress(&p, d_T1);   T1   = (float*)p;
    cudaGetSymbolAddress(&p, d_PT);   PT   = (float*)p;

    // 1. adj -> code
    code_kernel<<<16384, 256>>>((const float4*)adj);
    // 2. gathered code matrix + transpose
    gather_kernel<<<dim3(NE / 32, NE / 32), dim3(32, 32)>>>(u, v);
    // 3. rating-axis cumsums
    cumsum_kernel<<<(NUI * H0) / 256, 256>>>(u_w, cu, NUI * H0);
    cumsum_kernel<<<(NVI * H0) / 256, 256>>>(v_w, cv, NVI * H0);
    // 4. zero accumulators (graph replays!)
    zero_kernel<<<1, 1>>>();
    // 5. graph conv (sparse gather-sum); writes z into cat[:, :256]
    conv_kernel<<<NE, 256>>>(cg,  v, cv, ucat);
    conv_kernel<<<NE, 256>>>(cgT, u, cu, vcat);
    // 6. feature MLPs into cat[:, 256:768]
    gemm_kernel<<<dim3(DIN / 64, NE / 64), 256>>>(ufeat, SIDE, u, Wu1, SIDE, bu1,
                                                  ucat + H0, CATW, SIDE, 1);
    gemm_kernel<<<dim3(DIN / 64, NE / 64), 256>>>(vfeat, SIDE, v, Wv1, SIDE, bv1,
                                                  vcat + H0, CATW, SIDE, 1);
    // 7. hidden projections
    gemm_kernel<<<dim3(H1 / 64, NE / 64), 256>>>(ucat, CATW, nullptr, Wu2, CATW, nullptr,
                                                 uh, H1, CATW, 1);
    gemm_kernel<<<dim3(H1 / 64, NE / 64), 256>>>(vcat, CATW, nullptr, Wv2, CATW, nullptr,
                                                 vh, H1, CATW, 1);
    // 8. T_b = u_h @ P[b]
    transP_kernel<<<128, 256>>>(P);
    gemm_kernel<<<dim3(H1 / 64, NE / 64), 256>>>(uh, H1, nullptr, PT, H1, nullptr,
                                                 T0, H1, H1, 0);
    gemm_kernel<<<dim3(H1 / 64, NE / 64), 256>>>(uh, H1, nullptr, PT + H1 * H1, H1, nullptr,
                                                 T1, H1, H1, 0);
    // 9. fused decoder + softmax + losses
    final_kernel<<<dim3(NE / 64, NE / 64), 256>>>(a, out);
    // 10. scalars
    if (out_size >= NE * NE + 2) fin_kernel<<<1, 1>>>(out);
}